// round 5
// baseline (speedup 1.0000x reference)
#include <cuda_runtime.h>
#include <math.h>

#define NB 1024
#define NC 100000
#define THREADS 256
#define SPLIT 2                 // CTAs per row
#define GRID (NB * SPLIT)       // 2048
#define HALF (NC / SPLIT)       // 50000 floats per CTA

// scratch: per-CTA partial exp-sums + completion counter (zero-init at load)
static __device__ float g_part[GRID];
static __device__ unsigned int g_done;

__device__ __forceinline__ float ex2_fast(float x) {
    float y;
    asm("ex2.approx.ftz.f32 %0, %1;" : "=f"(y) : "f"(x));
    return y;
}

// 64 * log2(e)
#define K2 92.33248261625200f
#define LOG2E 1.4426950408889634f

__device__ __forceinline__ float term(float v) {
    float c = fminf(fmaxf(v, -1.0f), 1.0f);
    return ex2_fast(fmaf(c, K2, -K2));   // exp(64*c - 64)
}

__global__ void __launch_bounds__(THREADS)
fused_loss_kernel(const float* __restrict__ x,
                  const int* __restrict__ label,
                  const float* __restrict__ margin,
                  float* __restrict__ out) {
    const int bid  = blockIdx.x;
    const int row  = bid >> 1;
    const int half = bid & 1;
    const float4* __restrict__ p =
        reinterpret_cast<const float4*>(x + (size_t)row * NC + (size_t)half * HALF);
    const int n4 = HALF / 4;  // 12500

    float s = 0.0f;
    #pragma unroll 4
    for (int i = threadIdx.x; i < n4; i += THREADS) {
        float4 v = p[i];
        s += term(v.x) + term(v.y) + term(v.z) + term(v.w);
    }

    // block reduction
    __shared__ float red[THREADS / 32];
    __shared__ bool amLast;
    const int lane = threadIdx.x & 31;
    const int wid  = threadIdx.x >> 5;
    #pragma unroll
    for (int o = 16; o; o >>= 1) s += __shfl_xor_sync(0xFFFFFFFFu, s, o);
    if (lane == 0) red[wid] = s;
    __syncthreads();

    if (threadIdx.x == 0) {
        float t = 0.0f;
        #pragma unroll
        for (int w = 0; w < THREADS / 32; w++) t += red[w];
        g_part[bid] = t;
        __threadfence();
        unsigned int done = atomicAdd(&g_done, 1u);
        amLast = (done == (unsigned int)(GRID - 1));
    }
    __syncthreads();

    // last block to finish: per-row nll for all rows + mean (deterministic order)
    if (amLast) {
        __threadfence();
        float acc = 0.0f;
        #pragma unroll
        for (int k = 0; k < NB / THREADS; k++) {        // 4 rows per thread
            const int r = threadIdx.x + k * THREADS;
            float t = g_part[2 * r] + g_part[2 * r + 1];

            int lb = label[r];
            const bool valid = (lb >= 0);
            int tgt = valid ? lb : 0;
            tgt = min(max(tgt, 0), NC - 1);
            const float mg = valid ? margin[r] : 0.0f;

            float xt = x[(size_t)r * NC + tgt];
            float c  = fminf(fmaxf(xt, -1.0f), 1.0f);
            float l_mod = 64.0f * cosf(acosf(c) + mg);

            // replace target term: subtract original, add modified
            float stot = t - ex2_fast(fmaf(c, K2, -K2))
                           + ex2_fast((l_mod - 64.0f) * LOG2E);

            acc += 64.0f + logf(stot) - l_mod;          // nll
        }

        #pragma unroll
        for (int o = 16; o; o >>= 1) acc += __shfl_xor_sync(0xFFFFFFFFu, acc, o);
        if (lane == 0) red[wid] = acc;
        __syncthreads();
        if (wid == 0) {
            float u = (lane < THREADS / 32) ? red[lane] : 0.0f;
            #pragma unroll
            for (int o = (THREADS / 64); o; o >>= 1)
                u += __shfl_xor_sync(0xFFFFFFFFu, u, o);
            if (lane == 0) {
                out[0] = u * (1.0f / (float)NB);
                g_done = 0;                              // reset for graph replay
            }
        }
    }
}

extern "C" void kernel_launch(void* const* d_in, const int* in_sizes, int n_in,
                              void* d_out, int out_size) {
    const float* x      = (const float*)d_in[0];
    const int*   label  = (const int*)d_in[1];
    const float* margin = (const float*)d_in[2];
    float*       out    = (float*)d_out;

    fused_loss_kernel<<<GRID, THREADS>>>(x, label, margin, out);
}